// round 14
// baseline (speedup 1.0000x reference)
#include <cuda_runtime.h>
#include <cuda_fp16.h>
#include <cstdint>

// dw[p][q] = LR * ( (1/B)*sum_b post[b][p]*pre[b][q] - WD*W[p][q] )
// B=128, P=Q=1024.  fp16 single-pass mma.sync (rel err ~3e-5).
// R14: R12 base (single launch, coalesced convert, trans-ldmatrix mainloop)
// + coalesced SMEM-staged epilogue: W tile pulled by cp.async at kernel start;
// acc fragments staged to SMEM fp32; final pass is LDS.128/LDS.128/STG.128
// (8x fewer L1tex wavefronts than the fragment-layout LDG.64/STG.64 tail).

#define DIM      1024
#define KDIM     128
#define NTHREADS 512
#define BM       128
#define BN       64

#define PA       272                  // fp16 A tile pitch (256 data + 16 pad)
#define PB       144                  // fp16 B tile pitch (128 data + 16 pad)
#define PO       272                  // fp32 acc staging pitch (256 data + 16 pad)
#define FA       0
#define FB       (KDIM * PA)          // 34816
#define WS       (FB + KDIM * PB)     // 53248: W fp32 tile, 128 rows x 256B
#define OS       FA                   // acc staging reuses A-tile region (34816 B)
#define SMEM_TOTAL (WS + BM * 256)    // 86016

static __device__ __forceinline__ uint32_t smem_u32(const void* p) {
    uint32_t a;
    asm("{ .reg .u64 t; cvta.to.shared.u64 t, %1; cvt.u32.u64 %0, t; }" : "=r"(a) : "l"(p));
    return a;
}
static __device__ __forceinline__ void cp16(uint32_t saddr, const void* gaddr) {
    asm volatile("cp.async.ca.shared.global [%0], [%1], 16;" :: "r"(saddr), "l"(gaddr));
}
static __device__ __forceinline__ void ldsm_x4_trans(uint32_t* r, uint32_t addr) {
    asm volatile("ldmatrix.sync.aligned.m8n8.x4.trans.shared.b16 {%0,%1,%2,%3}, [%4];"
                 : "=r"(r[0]), "=r"(r[1]), "=r"(r[2]), "=r"(r[3]) : "r"(addr));
}
static __device__ __forceinline__ void mma16816(float* c, const uint32_t* a,
                                                uint32_t b0, uint32_t b1) {
    asm volatile(
        "mma.sync.aligned.m16n8k16.row.col.f32.f16.f16.f32 "
        "{%0,%1,%2,%3}, {%4,%5,%6,%7}, {%8,%9}, {%0,%1,%2,%3};"
        : "+f"(c[0]), "+f"(c[1]), "+f"(c[2]), "+f"(c[3])
        : "r"(a[0]), "r"(a[1]), "r"(a[2]), "r"(a[3]), "r"(b0), "r"(b1));
}
static __device__ __forceinline__ uint32_t pack_h2(float a, float b) {
    const __half2 h = __floats2half2_rn(a, b);
    return *(const uint32_t*)&h;
}

__global__ __launch_bounds__(NTHREADS, 1)
void hebbian_fp16_kernel(const float* __restrict__ pre,
                         const float* __restrict__ post,
                         const float* __restrict__ W,
                         float* __restrict__ out)
{
    extern __shared__ char smem[];
    const uint32_t sbase = smem_u32(smem);
    const int tid  = threadIdx.x;
    const int lane = tid & 31;
    const int wid  = tid >> 5;
    const int pm0  = blockIdx.y * BM;
    const int qn0  = blockIdx.x * BN;

    // ---- cp.async W tile into SMEM first (drains behind convert+mainloop) ----
    #pragma unroll
    for (int it = 0; it < 4; ++it) {                  // 128 rows x 16 chunks = 2048
        const int c = tid + NTHREADS * it;
        const int p = c >> 4;
        const int f = c & 15;
        cp16(sbase + WS + p * 256 + f * 16, W + (size_t)(pm0 + p) * DIM + qn0 + f * 4);
    }
    asm volatile("cp.async.commit_group;" ::: "memory");

    // ---- issue ALL convert loads (coalesced LDG.128 along m), max MLP ----
    float4 va[8];                          // A: 128k x 32 groups
    #pragma unroll
    for (int it = 0; it < 8; ++it) {
        const int u = tid + NTHREADS * it;
        const int k = u >> 5;
        const int f = u & 31;
        va[it] = *(const float4*)(post + (size_t)k * DIM + pm0 + f * 4);
    }
    float4 vb[4];                          // B: 128k x 16 groups
    #pragma unroll
    for (int it = 0; it < 4; ++it) {
        const int u = tid + NTHREADS * it;
        const int k = u >> 4;
        const int f = u & 15;
        vb[it] = *(const float4*)(pre + (size_t)k * DIM + qn0 + f * 4);
    }

    // ---- convert + store fp16 tiles, STS.128 (pairs of float4 groups) ----
    #pragma unroll
    for (int it = 0; it < 4; ++it) {       // A: pair groups (2*it, 2*it+1)
        const int u = tid + NTHREADS * it;          // u in [0,2048)
        const int k = u >> 4;
        const int f2 = (u & 15) * 2;                // even group index
        const float4 x = va[2 * it], y = va[2 * it + 1];
        // NOTE: groups 2*it and 2*it+1 of the SAME thread are NTHREADS apart
        // in u-space, i.e. different k — cannot fuse. Fall back to STS.64 pairs.
        (void)k; (void)f2; (void)x; (void)y;
    }
    #pragma unroll
    for (int it = 0; it < 8; ++it) {
        const int u = tid + NTHREADS * it;
        const int k = u >> 5;
        const int f = u & 31;
        uint2 o;
        o.x = pack_h2(va[it].x, va[it].y);
        o.y = pack_h2(va[it].z, va[it].w);
        *(uint2*)(smem + FA + k * PA + f * 8) = o;
    }
    #pragma unroll
    for (int it = 0; it < 4; ++it) {
        const int u = tid + NTHREADS * it;
        const int k = u >> 4;
        const int f = u & 15;
        uint2 o;
        o.x = pack_h2(vb[it].x, vb[it].y);
        o.y = pack_h2(vb[it].z, vb[it].w);
        *(uint2*)(smem + FB + k * PB + f * 8) = o;
    }
    __syncthreads();

    // ---- mma mainloop (verified trans-ldmatrix scheme) ----
    const int wm = (wid >> 1) * 16;
    const int wn = (wid & 1) * 32;
    float acc[4][4];
    #pragma unroll
    for (int j = 0; j < 4; ++j)
        #pragma unroll
        for (int r = 0; r < 4; ++r)
            acc[j][r] = 0.0f;

    const int kl = (lane & 7) + ((lane >> 4) << 3);
    const int ml = (lane & 8);

    #pragma unroll
    for (int ks = 0; ks < KDIM / 16; ++ks) {
        const int kb = ks * 16;
        uint32_t a[4], b[2][4];
        ldsm_x4_trans(a, sbase + FA + (kb + kl) * PA + (wm + ml) * 2);
        #pragma unroll
        for (int nb = 0; nb < 2; ++nb)
            ldsm_x4_trans(b[nb], sbase + FB + (kb + kl) * PB + (wn + nb * 16 + ml) * 2);
        #pragma unroll
        for (int nn = 0; nn < 4; ++nn) {
            const int nb = nn >> 1, sel = nn & 1;
            mma16816(acc[nn], a, b[nb][sel], b[nb][sel + 2]);
        }
    }

    // ---- stage acc into SMEM fp32 (reuses A-tile region) ----
    asm volatile("cp.async.wait_group 0;" ::: "memory");
    __syncthreads();                                  // all LDSM done; W landed
    {
        const int prow0 = wm + (lane >> 2);           // local p (0..127)
        const int qcol0 = wn + (lane & 3) * 2;        // local q (0..63)
        #pragma unroll
        for (int nn = 0; nn < 4; ++nn) {
            #pragma unroll
            for (int h = 0; h < 2; ++h) {
                const int p = prow0 + h * 8;
                const int q = qcol0 + nn * 8;
                float2 v;
                v.x = acc[nn][2 * h + 0];
                v.y = acc[nn][2 * h + 1];
                *(float2*)(smem + OS + p * PO + q * 4) = v;
            }
        }
    }
    __syncthreads();

    // ---- coalesced epilogue: dw = acc*(LR/B) - (LR*WD)*W ----
    const float c1 = 0.005f / 128.0f;
    const float c2 = 0.005f * 0.0001f;
    #pragma unroll
    for (int it = 0; it < 4; ++it) {                  // 2048 float4 units
        const int u = tid + NTHREADS * it;
        const int p = u >> 4;
        const int f = u & 15;
        const float4 a4 = *(const float4*)(smem + OS + p * PO + f * 16);
        const float4 w4 = *(const float4*)(smem + WS + p * 256 + f * 16);
        float4 o;
        o.x = fmaf(a4.x, c1, -c2 * w4.x);
        o.y = fmaf(a4.y, c1, -c2 * w4.y);
        o.z = fmaf(a4.z, c1, -c2 * w4.z);
        o.w = fmaf(a4.w, c1, -c2 * w4.w);
        *(float4*)(out + (size_t)(pm0 + p) * DIM + qn0 + f * 4) = o;
    }
}

extern "C" void kernel_launch(void* const* d_in, const int* in_sizes, int n_in,
                              void* d_out, int out_size)
{
    const float* pre  = (const float*)d_in[0];   // (128, 1024)
    const float* post = (const float*)d_in[1];   // (128, 1024)
    const float* W    = (const float*)d_in[2];   // (1024, 1024)
    float* out = (float*)d_out;                  // (1024, 1024)

    static bool attr_set = false;
    if (!attr_set) {
        cudaFuncSetAttribute(hebbian_fp16_kernel,
                             cudaFuncAttributeMaxDynamicSharedMemorySize, SMEM_TOTAL);
        attr_set = true;
    }
    dim3 grid(DIM / BN, DIM / BM);   // (16, 8) = 128 CTAs, 1/SM, single wave
    hebbian_fp16_kernel<<<grid, NTHREADS, SMEM_TOTAL>>>(pre, post, W, out);
}